// round 9
// baseline (speedup 1.0000x reference)
#include <cuda_runtime.h>

#define WH    128
#define NPIX  (WH*WH)      // 16384
#define NB    2
#define NBK   32           // 2 batches x 16 instances
#define NBLK  32           // persistent grid, 16 blocks per batch
#define NBB   16           // blocks per batch
#define TPB   1024         // 8 rows per block

// Scratch (no allocations allowed)
__device__ unsigned g_max[NBK];      // per-(b,k) max(d) as ordered uint (reset by designated)
__device__ float    g_part[NBLK];    // per-block loss partials
__device__ float    g_bsum[NB * 32]; // per-batch sums (line-separated)
__device__ unsigned g_barA[64];      // barrier1 counters: [0]=b0, [32]=b1
__device__ unsigned g_barB[64];      // barrier2 counters: [0]=b0, [32]=b1
__device__ unsigned g_fin = 0;       // 2-arrival final ticket (monotonic)

// Monotonic ticket barrier (replay-safe), n arrivals on counter c.
__device__ __forceinline__ void ticketbar(unsigned* c, unsigned n)
{
    __threadfence();
    __syncthreads();
    if (threadIdx.x == 0) {
        unsigned ticket = atomicAdd(c, 1u) + 1u;
        unsigned target = ((ticket + n - 1u) / n) * n;
        volatile unsigned* vc = c;
        while (*vc < target) { }
    }
    __syncthreads();
    __threadfence();
}

__global__ __launch_bounds__(TPB, 1) void fused_kernel(
    const float* __restrict__ pred,
    const int*   __restrict__ mask,
    const float* __restrict__ ign,
    float* __restrict__ out)
{
    const int tid = threadIdx.x;
    const int bx  = blockIdx.x;

    const int p  = bx * TPB + tid;        // pixel id 0..32767 (row-major)
    const int b  = p >> 14;               // batch (16 blocks per batch)
    const int xy = p & (NPIX - 1);
    const int i0 = xy >> 7;               // this pixel's row
    const int j  = xy & 127;
    const int r0 = tid >> 7;              // 0..7: which of the block's 8 rows

    __shared__ unsigned char s_lab[8][WH];
    __shared__ float    s_rm2[8][WH];
    __shared__ unsigned smax[16];
    __shared__ float    s_gm[16];
    __shared__ float    ws[32];

    // ---- Early prefetch (independent; hides DRAM/L2 latency) ----------------
    const float* pp = pred + b * 8 * NPIX + xy;
    float pr[8];
    #pragma unroll
    for (int c = 0; c < 8; c++) pr[c] = pp[c * NPIX];
    const float w_ign = ign[p];

    if (tid < 16) smax[tid] = 0u;

    // ---- Own label + vertical ±8 neighbors straight from global -------------
    // Fixed neighbor row, lanes consecutive j -> 128B coalesced LDG, all
    // independent: one L2 latency window.
    const int* gpix = mask + b * NPIX + i0 * WH + j;
    const int lab = *gpix;
    s_lab[r0][j] = (unsigned char)lab;

    {
        unsigned upb = 0, dnb = 0;
        #pragma unroll
        for (int t = 1; t <= 8; t++) {
            if (i0 - t >= 0 && __ldg(gpix - t * WH) == lab) upb |= 1u << (t - 1);
            if (i0 + t < WH && __ldg(gpix + t * WH) == lab) dnb |= 1u << (t - 1);
        }
        int ru = __ffs(~upb) - 1;       // consecutive same-label run upward
        if (ru == 8) { while (i0 - 1 - ru >= 0 && gpix[-(1 + ru) * WH] == lab) ru++; }
        const int du = (i0 - 1 - ru >= 0) ? ru + 1 : 1000;

        int rd = __ffs(~dnb) - 1;       // downward
        if (rd == 8) { while (i0 + 1 + rd < WH && gpix[(1 + rd) * WH] == lab) rd++; }
        const int dd = (i0 + 1 + rd < WH) ? rd + 1 : 1000;

        const int md = min(du, dd);
        s_rm2[r0][j] = (md >= WH) ? 1e9f : (float)(md * md);
    }
    __syncthreads();

    // ---- Adaptive row envelope (bit-exact early cutoff) ---------------------
    // d^2 = min_{j'} v[j'] + (j-j')^2, v[j'] = (lab'==lab ? rm2[j'] : 0) >= 0.
    float d = 0.f;
    {
        const unsigned char* mrow = s_lab[r0];
        const float*         vrow = s_rm2[r0];
        const unsigned char lb = (unsigned char)lab;
        float m = (lab > 0) ? vrow[j] : 0.f;               // o = 0 term
        for (int o = 1; o < WH; o += 2) {
            float o2a = (float)(o * o);                    // exact integer
            if (__all_sync(0xFFFFFFFFu, o2a >= m)) break;
            int jl = j - o, jr = j + o;
            if (jl >= 0) { float v = (mrow[jl] == lb) ? vrow[jl] : 0.f; m = fminf(m, o2a + v); }
            if (jr < WH) { float v = (mrow[jr] == lb) ? vrow[jr] : 0.f; m = fminf(m, o2a + v); }
            int o1 = o + 1; float o2b = (float)(o1 * o1);
            int jl1 = j - o1, jr1 = j + o1;
            if (jl1 >= 0) { float v = (mrow[jl1] == lb) ? vrow[jl1] : 0.f; m = fminf(m, o2b + v); }
            if (jr1 < WH) { float v = (mrow[jr1] == lb) ? vrow[jr1] : 0.f; m = fminf(m, o2b + v); }
        }
        if (lab > 0) {
            d = __fsqrt_rn(m);                              // IEEE sqrt
            atomicMax(&smax[lab - 1], __float_as_uint(d));  // shared; d>=0
        }
    }
    __syncthreads();
    if (tid < 16 && smax[tid]) atomicMax(&g_max[(b << 4) + tid], smax[tid]);  // REDG

    // ---- Pre-barrier: gt zeros (drain during barrier) + both L1 candidates --
    float* go = out + 1 + b * 8 * NPIX + xy;               // out[0] = loss
    #pragma unroll
    for (int c = 0; c < 8; c++) go[c * NPIX] = 0.f;

    float l1a[8], l1b[8];
    #pragma unroll
    for (int c = 0; c < 8; c++) {
        float da = pr[c];
        float aa = fabsf(da);
        l1a[c] = (aa < 1.f) ? 0.5f * da * da : (aa - 0.5f);
        float db = pr[c] - 1.f;
        float ab = fabsf(db);
        l1b[c] = (ab < 1.f) ? 0.5f * db * db : (ab - 0.5f);
    }

    ticketbar(&g_barA[b * 32], NBB);   // 16-arrival barrier: maxima final

    // ---- Final maxima for this batch (single L2 window) ---------------------
    if (tid < 16) s_gm[tid] = __uint_as_float(__ldcg(&g_max[(b << 4) + tid]));
    __syncthreads();

    // ---- Bin select + single hit store + loss (bit-exact term order) --------
    int c0 = -1;
    if (lab > 0) {
        float mv = s_gm[lab - 1];
        float dn = (mv > 0.f) ? __fdiv_rn(d, mv) : d;      // IEEE div
        if (dn < 0.5f) dn = 0.0f;
        if (dn > 0.7f) dn = 1.0f;
        const float DDD[8] = {0.83f, 0.68f, 0.54f, 0.41f, 0.29f, 0.18f, 0.09f, 0.0f};
        c0 = 7;
        #pragma unroll
        for (int c = 0; c < 8; c++)
            if (dn >= DDD[c]) { c0 = c; break; }
        go[c0 * NPIX] = 1.f;         // same thread/address: ordered after the 0
    }

    float s = 0.f;
    #pragma unroll
    for (int c = 0; c < 8; c++)
        s += (c == c0) ? l1b[c] : l1a[c];                  // same terms, same order
    float contrib = w_ign * s * 0.125f;                    // mean over C=8

    #pragma unroll
    for (int off = 16; off; off >>= 1)
        contrib += __shfl_xor_sync(0xFFFFFFFFu, contrib, off);
    if ((tid & 31) == 0) ws[tid >> 5] = contrib;
    __syncthreads();
    if (tid < 32) {
        float v = ws[tid];
        #pragma unroll
        for (int off = 16; off; off >>= 1)
            v += __shfl_xor_sync(0xFFFFFFFFu, v, off);
        if (tid == 0) g_part[bx] = v;
    }

    ticketbar(&g_barB[b * 32], NBB);   // 16-arrival barrier: partials final

    // ---- Designated block per batch: batch sum + 2-arrival finale ----------
    if ((bx & (NBB - 1)) == 0) {
        // All this batch's g_max reads done (they precede barrier-B arrival).
        if (tid < 16) g_max[(b << 4) + tid] = 0u;          // reset for next replay

        if (tid < 32) {
            float v = (tid < NBB) ? __ldcg(&g_part[b * NBB + tid]) : 0.f;
            #pragma unroll
            for (int off = 8; off; off >>= 1)              // reduce 16 values
                v += __shfl_xor_sync(0xFFFFFFFFu, v, off);
            if (tid == 0) {
                __stcg(&g_bsum[b * 32], v);
                __threadfence();
                unsigned ticket = atomicAdd(&g_fin, 1u) + 1u;
                unsigned target = ((ticket + 1u) / 2u) * 2u;
                volatile unsigned* vf = &g_fin;
                while (*vf < target) { }
                __threadfence();
                float s0 = __ldcg(&g_bsum[0]);
                float s1 = __ldcg(&g_bsum[32]);
                out[0] = (s0 + s1) * (1.f / (float)(NB * NPIX));  // both write same value
            }
        }
    }
}

extern "C" void kernel_launch(void* const* d_in, const int* in_sizes, int n_in,
                              void* d_out, int out_size)
{
    const float* pred = (const float*)d_in[0];   // [2,8,128,128] f32
    const int*   mask = (const int*)  d_in[1];   // [2,128,128]   i32
    const float* ign  = (const float*)d_in[2];   // [2,128,128]   f32
    float* out = (float*)d_out;                  // [0]=loss, [1..]=gt

    fused_kernel<<<NBLK, TPB>>>(pred, mask, ign, out);
}

// round 10
// speedup vs baseline: 1.3692x; 1.3692x over previous
#include <cuda_runtime.h>

#define WH    128
#define NPIX  (WH*WH)      // 16384
#define NB    2
#define NBK   32           // 2 batches x 16 instances
#define NBLK  128          // persistent grid, 64 blocks per batch
#define TPB   256          // 2 rows per block

// Scratch (no allocations allowed)
__device__ unsigned g_max[NBK];          // per-(b,k) max(d) as ordered uint (reset by last block)
__device__ float    g_part[NBLK];        // per-block loss partials
__device__ unsigned g_cnt[64];           // [0]=batch0 barrier, [32]=batch1 (separate lines)
__device__ unsigned g_done = 0;          // monotonic arrival counter (final reduce)

// Per-batch barrier: monotonic ticket counter, replay-safe, 64 arrivals.
__device__ __forceinline__ void batchbar(int b)
{
    __threadfence();
    __syncthreads();
    if (threadIdx.x == 0) {
        unsigned* c = &g_cnt[b * 32];
        unsigned ticket = atomicAdd(c, 1u) + 1u;
        unsigned target = ((ticket + 63u) / 64u) * 64u;
        volatile unsigned* vc = c;
        while (*vc < target) { }
    }
    __syncthreads();
    __threadfence();
}

__global__ __launch_bounds__(TPB, 1) void fused_kernel(
    const float* __restrict__ pred,
    const int*   __restrict__ mask,
    const float* __restrict__ ign,
    float* __restrict__ out)
{
    const int tid = threadIdx.x;
    const int bx  = blockIdx.x;

    const int p  = bx * TPB + tid;        // pixel id 0..32767 (row-major)
    const int b  = p >> 14;               // batch (64 blocks per batch)
    const int xy = p & (NPIX - 1);
    const int i0 = xy >> 7;               // this pixel's row
    const int j  = xy & 127;
    const int r0 = tid >> 7;              // 0/1: which of the block's 2 rows

    __shared__ unsigned char s_lab[2][WH];
    __shared__ float    s_rm2[2][WH];
    __shared__ unsigned smax[16];
    __shared__ float    ws[8];
    __shared__ int      s_last;

    // ---- Early prefetch (independent; hides DRAM/L2 latency) ----------------
    const float* pp = pred + b * 8 * NPIX + xy;
    float pr[8];
    #pragma unroll
    for (int c = 0; c < 8; c++) pr[c] = pp[c * NPIX];
    const float w_ign = ign[p];

    if (tid < 16) smax[tid] = 0u;

    // ---- Own label + vertical ±8 neighbors straight from global -------------
    // Fixed neighbor row, lanes consecutive j -> 128B coalesced LDG, all 17
    // loads independent: one L2 latency window.
    const int* gpix = mask + b * NPIX + i0 * WH + j;
    const int lab = *gpix;
    s_lab[r0][j] = (unsigned char)lab;

    {
        unsigned upb = 0, dnb = 0;
        #pragma unroll
        for (int t = 1; t <= 8; t++) {
            if (i0 - t >= 0 && __ldg(gpix - t * WH) == lab) upb |= 1u << (t - 1);
            if (i0 + t < WH && __ldg(gpix + t * WH) == lab) dnb |= 1u << (t - 1);
        }
        int ru = __ffs(~upb) - 1;       // consecutive same-label run upward
        if (ru == 8) { while (i0 - 1 - ru >= 0 && gpix[-(1 + ru) * WH] == lab) ru++; }
        const int du = (i0 - 1 - ru >= 0) ? ru + 1 : 1000;

        int rd = __ffs(~dnb) - 1;       // downward
        if (rd == 8) { while (i0 + 1 + rd < WH && gpix[(1 + rd) * WH] == lab) rd++; }
        const int dd = (i0 + 1 + rd < WH) ? rd + 1 : 1000;

        const int md = min(du, dd);
        s_rm2[r0][j] = (md >= WH) ? 1e9f : (float)(md * md);
    }
    __syncthreads();

    // ---- Adaptive row envelope (bit-exact early cutoff) ---------------------
    // d^2 = min_{j'} v[j'] + (j-j')^2, v[j'] = (lab'==lab ? rm2[j'] : 0) >= 0.
    // Break when o^2 >= m for all lanes at the smaller o of each pair
    // (conservative; fminf over identical candidate set -> bit-identical).
    float d = 0.f;
    {
        const unsigned char* mrow = s_lab[r0];
        const float*         vrow = s_rm2[r0];
        const unsigned char lb = (unsigned char)lab;
        float m = (lab > 0) ? vrow[j] : 0.f;               // o = 0 term
        for (int o = 1; o < WH; o += 2) {
            float o2a = (float)(o * o);                    // exact integer
            if (__all_sync(0xFFFFFFFFu, o2a >= m)) break;
            int jl = j - o, jr = j + o;
            if (jl >= 0) { float v = (mrow[jl] == lb) ? vrow[jl] : 0.f; m = fminf(m, o2a + v); }
            if (jr < WH) { float v = (mrow[jr] == lb) ? vrow[jr] : 0.f; m = fminf(m, o2a + v); }
            int o1 = o + 1; float o2b = (float)(o1 * o1);
            int jl1 = j - o1, jr1 = j + o1;
            if (jl1 >= 0) { float v = (mrow[jl1] == lb) ? vrow[jl1] : 0.f; m = fminf(m, o2b + v); }
            if (jr1 < WH) { float v = (mrow[jr1] == lb) ? vrow[jr1] : 0.f; m = fminf(m, o2b + v); }
        }
        if (lab > 0) {
            d = __fsqrt_rn(m);                              // IEEE sqrt
            atomicMax(&smax[lab - 1], __float_as_uint(d));  // shared; d>=0
        }
    }
    __syncthreads();
    if (tid < 16) atomicMax(&g_max[(b << 4) + tid], smax[tid]);  // REDG, fire-and-forget

    // ---- Pre-barrier: gt zeros (drain during barrier) + l1(g=0) candidates --
    float* go = out + 1 + b * 8 * NPIX + xy;               // out[0] = loss
    #pragma unroll
    for (int c = 0; c < 8; c++) go[c * NPIX] = 0.f;

    float l1a[8];
    #pragma unroll
    for (int c = 0; c < 8; c++) {
        float da = pr[c];
        float aa = fabsf(da);
        l1a[c] = (aa < 1.f) ? 0.5f * da * da : (aa - 0.5f);
    }

    batchbar(b);   // only this batch's 64 blocks

    // ---- Bin select + single hit store + loss (bit-exact term order) --------
    int   c0  = -1;
    float l1h = 0.f;
    if (lab > 0) {
        float mv = __uint_as_float(__ldcg(&g_max[(b << 4) + lab - 1]));  // direct, no staging
        float dn = (mv > 0.f) ? __fdiv_rn(d, mv) : d;      // IEEE div
        if (dn < 0.5f) dn = 0.0f;
        if (dn > 0.7f) dn = 1.0f;
        const float DDD[8] = {0.83f, 0.68f, 0.54f, 0.41f, 0.29f, 0.18f, 0.09f, 0.0f};
        c0 = 7;
        #pragma unroll
        for (int c = 0; c < 8; c++)
            if (dn >= DDD[c]) { c0 = c; break; }
        go[c0 * NPIX] = 1.f;          // same thread/address: ordered after the 0

        float db = pr[c0] - 1.f;      // l1 for the hit channel (g=1)
        float ab = fabsf(db);
        l1h = (ab < 1.f) ? 0.5f * db * db : (ab - 0.5f);
    }

    float s = 0.f;
    #pragma unroll
    for (int c = 0; c < 8; c++)
        s += (c == c0) ? l1h : l1a[c];                     // same terms, same order
    float contrib = w_ign * s * 0.125f;                    // mean over C=8

    #pragma unroll
    for (int off = 16; off; off >>= 1)
        contrib += __shfl_xor_sync(0xFFFFFFFFu, contrib, off);
    if ((tid & 31) == 0) ws[tid >> 5] = contrib;
    __syncthreads();
    if (tid == 0) {
        float tsum = 0.f;
        #pragma unroll
        for (int u = 0; u < 8; u++) tsum += ws[u];
        g_part[bx] = tsum;
        __threadfence();
        unsigned t = atomicAdd(&g_done, 1u);
        s_last = (((t + 1u) & (NBLK - 1u)) == 0u);         // last arrival this replay
    }
    __syncthreads();

    // ---- Last block: reset maxima for next replay + deterministic reduction -
    if (s_last) {
        __threadfence();
        if (tid < NBK) g_max[tid] = 0u;
        float v = 0.f;
        if (tid < NBLK) {
            v = __ldcg(&g_part[tid]);
            #pragma unroll
            for (int off = 16; off; off >>= 1)
                v += __shfl_xor_sync(0xFFFFFFFFu, v, off);
            if ((tid & 31) == 0) ws[tid >> 5] = v;
        }
        __syncthreads();
        if (tid == 0)
            out[0] = ((ws[0] + ws[1]) + (ws[2] + ws[3])) * (1.f / (float)(NB * NPIX));
    }
}

extern "C" void kernel_launch(void* const* d_in, const int* in_sizes, int n_in,
                              void* d_out, int out_size)
{
    const float* pred = (const float*)d_in[0];   // [2,8,128,128] f32
    const int*   mask = (const int*)  d_in[1];   // [2,128,128]   i32
    const float* ign  = (const float*)d_in[2];   // [2,128,128]   f32
    float* out = (float*)d_out;                  // [0]=loss, [1..]=gt

    fused_kernel<<<NBLK, TPB>>>(pred, mask, ign, out);
}

// round 11
// speedup vs baseline: 1.4018x; 1.0238x over previous
#include <cuda_runtime.h>

#define WH    128
#define NPIX  (WH*WH)      // 16384
#define NB    2
#define NBK   32           // 2 batches x 16 instances
#define NBLK  128          // persistent grid, 64 blocks per batch
#define TPB   256          // 2 rows per block

// Scratch (no allocations allowed). All counters monotonic (replay-safe),
// each on its own 128B line to land in distinct LTS slices.
__device__ unsigned g_max[NBK];          // per-(b,k) max(d) as ordered uint (reset by last block)
__device__ float    g_part[NBLK];        // per-block loss partials
__device__ unsigned g_bgrp[NB * 8 * 32]; // barrier group counters (8 per batch)
__device__ unsigned g_btop[NB * 32];     // barrier top counters (1 per batch)
__device__ unsigned g_dgrp[16 * 32];     // done group counters (16 x 8 blocks)
__device__ unsigned g_dtop = 0;          // done top counter (16 arrivals)

// Per-batch hierarchical ticket barrier: 8 groups of 8 -> top of 8.
// Worst same-address chain: 8 + 8 atomics instead of 64.
__device__ __forceinline__ void batchbar(int b, int bx)
{
    __threadfence();
    __syncthreads();
    if (threadIdx.x == 0) {
        const int grp = (bx >> 3) & 7;
        unsigned* gc = &g_bgrp[(b * 8 + grp) * 32];
        unsigned t = atomicAdd(gc, 1u) + 1u;
        unsigned epoch = (t + 7u) >> 3;            // this replay's epoch
        unsigned* tc = &g_btop[b * 32];
        if ((t & 7u) == 0u) atomicAdd(tc, 1u);     // group-last forwards arrival
        unsigned target = epoch * 8u;              // top gains 8 per epoch
        volatile unsigned* vt = tc;
        while (*vt < target) { }
    }
    __syncthreads();
    __threadfence();
}

__global__ __launch_bounds__(TPB, 1) void fused_kernel(
    const float* __restrict__ pred,
    const int*   __restrict__ mask,
    const float* __restrict__ ign,
    float* __restrict__ out)
{
    const int tid = threadIdx.x;
    const int bx  = blockIdx.x;

    const int p  = bx * TPB + tid;        // pixel id 0..32767 (row-major)
    const int b  = p >> 14;               // batch (64 blocks per batch)
    const int xy = p & (NPIX - 1);
    const int i0 = xy >> 7;               // this pixel's row
    const int j  = xy & 127;
    const int r0 = tid >> 7;              // 0/1: which of the block's 2 rows

    __shared__ unsigned char s_lab[2][WH];
    __shared__ float    s_rm2[2][WH];
    __shared__ unsigned smax[16];
    __shared__ float    s_gm[16];
    __shared__ float    ws[8];
    __shared__ int      s_last;

    // ---- Early prefetch (independent; hides DRAM/L2 latency) ----------------
    const float* pp = pred + b * 8 * NPIX + xy;
    float pr[8];
    #pragma unroll
    for (int c = 0; c < 8; c++) pr[c] = pp[c * NPIX];
    const float w_ign = ign[p];

    if (tid < 16) smax[tid] = 0u;

    // ---- Own label + vertical ±8 neighbors straight from global -------------
    // Fixed neighbor row, lanes consecutive j -> 128B coalesced LDG, all 17
    // loads independent: one L2 latency window.
    const int* gpix = mask + b * NPIX + i0 * WH + j;
    const int lab = *gpix;
    s_lab[r0][j] = (unsigned char)lab;

    {
        unsigned upb = 0, dnb = 0;
        #pragma unroll
        for (int t = 1; t <= 8; t++) {
            if (i0 - t >= 0 && __ldg(gpix - t * WH) == lab) upb |= 1u << (t - 1);
            if (i0 + t < WH && __ldg(gpix + t * WH) == lab) dnb |= 1u << (t - 1);
        }
        int ru = __ffs(~upb) - 1;       // consecutive same-label run upward
        if (ru == 8) { while (i0 - 1 - ru >= 0 && gpix[-(1 + ru) * WH] == lab) ru++; }
        const int du = (i0 - 1 - ru >= 0) ? ru + 1 : 1000;

        int rd = __ffs(~dnb) - 1;       // downward
        if (rd == 8) { while (i0 + 1 + rd < WH && gpix[(1 + rd) * WH] == lab) rd++; }
        const int dd = (i0 + 1 + rd < WH) ? rd + 1 : 1000;

        const int md = min(du, dd);
        s_rm2[r0][j] = (md >= WH) ? 1e9f : (float)(md * md);
    }
    __syncthreads();

    // ---- Adaptive row envelope (bit-exact early cutoff) ---------------------
    // d^2 = min_{j'} v[j'] + (j-j')^2, v[j'] = (lab'==lab ? rm2[j'] : 0) >= 0.
    float d = 0.f;
    {
        const unsigned char* mrow = s_lab[r0];
        const float*         vrow = s_rm2[r0];
        const unsigned char lb = (unsigned char)lab;
        float m = (lab > 0) ? vrow[j] : 0.f;               // o = 0 term
        for (int o = 1; o < WH; o += 2) {
            float o2a = (float)(o * o);                    // exact integer
            if (__all_sync(0xFFFFFFFFu, o2a >= m)) break;
            int jl = j - o, jr = j + o;
            if (jl >= 0) { float v = (mrow[jl] == lb) ? vrow[jl] : 0.f; m = fminf(m, o2a + v); }
            if (jr < WH) { float v = (mrow[jr] == lb) ? vrow[jr] : 0.f; m = fminf(m, o2a + v); }
            int o1 = o + 1; float o2b = (float)(o1 * o1);
            int jl1 = j - o1, jr1 = j + o1;
            if (jl1 >= 0) { float v = (mrow[jl1] == lb) ? vrow[jl1] : 0.f; m = fminf(m, o2b + v); }
            if (jr1 < WH) { float v = (mrow[jr1] == lb) ? vrow[jr1] : 0.f; m = fminf(m, o2b + v); }
        }
        if (lab > 0) {
            d = __fsqrt_rn(m);                              // IEEE sqrt
            atomicMax(&smax[lab - 1], __float_as_uint(d));  // shared; d>=0
        }
    }
    __syncthreads();
    if (tid < 16 && smax[tid]) atomicMax(&g_max[(b << 4) + tid], smax[tid]);  // REDG

    // ---- Pre-barrier: gt zeros (drain during barrier) + both L1 candidates --
    float* go = out + 1 + b * 8 * NPIX + xy;               // out[0] = loss
    #pragma unroll
    for (int c = 0; c < 8; c++) go[c * NPIX] = 0.f;

    float l1a[8], l1b[8];
    #pragma unroll
    for (int c = 0; c < 8; c++) {
        float da = pr[c];
        float aa = fabsf(da);
        l1a[c] = (aa < 1.f) ? 0.5f * da * da : (aa - 0.5f);
        float db = pr[c] - 1.f;
        float ab = fabsf(db);
        l1b[c] = (ab < 1.f) ? 0.5f * db * db : (ab - 0.5f);
    }

    batchbar(b, bx);   // hierarchical, only this batch's 64 blocks

    // ---- Final maxima for this batch (single L2 window) ---------------------
    if (tid < 16) s_gm[tid] = __uint_as_float(__ldcg(&g_max[(b << 4) + tid]));
    __syncthreads();

    // ---- Bin select + single hit store + loss (bit-exact term order) --------
    int c0 = -1;
    if (lab > 0) {
        float mv = s_gm[lab - 1];
        float dn = (mv > 0.f) ? __fdiv_rn(d, mv) : d;      // IEEE div
        if (dn < 0.5f) dn = 0.0f;
        if (dn > 0.7f) dn = 1.0f;
        const float DDD[8] = {0.83f, 0.68f, 0.54f, 0.41f, 0.29f, 0.18f, 0.09f, 0.0f};
        c0 = 7;
        #pragma unroll
        for (int c = 0; c < 8; c++)
            if (dn >= DDD[c]) { c0 = c; break; }
        go[c0 * NPIX] = 1.f;         // same thread/address: ordered after the 0
    }

    float s = 0.f;
    #pragma unroll
    for (int c = 0; c < 8; c++)
        s += (c == c0) ? l1b[c] : l1a[c];                  // same terms, same order
    float contrib = w_ign * s * 0.125f;                    // mean over C=8

    #pragma unroll
    for (int off = 16; off; off >>= 1)
        contrib += __shfl_xor_sync(0xFFFFFFFFu, contrib, off);
    if ((tid & 31) == 0) ws[tid >> 5] = contrib;
    __syncthreads();
    if (tid == 0) {
        float tsum = 0.f;
        #pragma unroll
        for (int u = 0; u < 8; u++) tsum += ws[u];
        g_part[bx] = tsum;
        __threadfence();
        // Hierarchical done-detection: 16 groups of 8 -> top of 16.
        const int dg = bx >> 3;
        unsigned t = atomicAdd(&g_dgrp[dg * 32], 1u) + 1u;
        int last = 0;
        if ((t & 7u) == 0u) {                              // group-last this epoch
            unsigned tt = atomicAdd(&g_dtop, 1u) + 1u;
            last = ((tt & 15u) == 0u);                     // global-last this epoch
        }
        s_last = last;
    }
    __syncthreads();

    // ---- Last block: reset maxima for next replay + deterministic reduction -
    if (s_last) {
        __threadfence();
        if (tid < NBK) g_max[tid] = 0u;
        float v = 0.f;
        if (tid < NBLK) {
            v = __ldcg(&g_part[tid]);
            #pragma unroll
            for (int off = 16; off; off >>= 1)
                v += __shfl_xor_sync(0xFFFFFFFFu, v, off);
            if ((tid & 31) == 0) ws[tid >> 5] = v;
        }
        __syncthreads();
        if (tid == 0)
            out[0] = ((ws[0] + ws[1]) + (ws[2] + ws[3])) * (1.f / (float)(NB * NPIX));
    }
}

extern "C" void kernel_launch(void* const* d_in, const int* in_sizes, int n_in,
                              void* d_out, int out_size)
{
    const float* pred = (const float*)d_in[0];   // [2,8,128,128] f32
    const int*   mask = (const int*)  d_in[1];   // [2,128,128]   i32
    const float* ign  = (const float*)d_in[2];   // [2,128,128]   f32
    float* out = (float*)d_out;                  // [0]=loss, [1..]=gt

    fused_kernel<<<NBLK, TPB>>>(pred, mask, ign, out);
}

// round 12
// speedup vs baseline: 1.7380x; 1.2399x over previous
#include <cuda_runtime.h>

#define WH    128
#define NPIX  (WH*WH)      // 16384
#define NB    2
#define NBK   32           // 2 batches x 16 instances
#define NBLK  128          // persistent grid, 64 blocks per batch
#define TPB   256          // 2 rows per block

// Scratch (no allocations allowed). Counters monotonic (replay-safe).
__device__ unsigned g_max[NBK];          // per-(b,k) max(d) as ordered uint (reset by last block)
__device__ float    g_part[NBLK];        // per-block loss partials
__device__ unsigned g_cnt[64];           // [0]=batch0 barrier, [32]=batch1 (separate lines)
__device__ unsigned g_done = 0;          // monotonic arrival counter (final reduce)

// Per-batch barrier: monotonic ticket counter, replay-safe, 64 arrivals.
// Release: fence before arrival. Acquire side intentionally omitted — all
// post-barrier cross-block reads use __ldcg (L2 point of coherence), and the
// producers' fences ordered their data into L2 before the counter arrival.
__device__ __forceinline__ void batchbar(int b)
{
    __threadfence();
    __syncthreads();
    if (threadIdx.x == 0) {
        unsigned* c = &g_cnt[b * 32];
        unsigned ticket = atomicAdd(c, 1u) + 1u;
        unsigned target = ((ticket + 63u) / 64u) * 64u;
        volatile unsigned* vc = c;
        while (*vc < target) { }
    }
    __syncthreads();
}

__global__ __launch_bounds__(TPB, 1) void fused_kernel(
    const float* __restrict__ pred,
    const int*   __restrict__ mask,
    const float* __restrict__ ign,
    float* __restrict__ out)
{
    const int tid = threadIdx.x;
    const int bx  = blockIdx.x;

    const int p  = bx * TPB + tid;        // pixel id 0..32767 (row-major)
    const int b  = p >> 14;               // batch (64 blocks per batch)
    const int xy = p & (NPIX - 1);
    const int i0 = xy >> 7;               // this pixel's row
    const int j  = xy & 127;
    const int r0 = tid >> 7;              // 0/1: which of the block's 2 rows

    __shared__ unsigned char s_lab[2][WH];
    __shared__ float    s_rm2[2][WH];
    __shared__ unsigned smax[16];
    __shared__ float    ws[8];
    __shared__ int      s_last;

    // ---- Critical-path loads FIRST: own label + vertical ±8 neighbors -------
    // Fixed neighbor row, lanes consecutive j -> 128B coalesced LDG; all 17
    // independent: one L2 latency window, issued before the (non-critical)
    // pred prefetch so the LSU serves them first.
    const int* gpix = mask + b * NPIX + i0 * WH + j;
    const int lab = *gpix;
    int nb[16];
    #pragma unroll
    for (int t = 1; t <= 8; t++) {
        nb[t - 1]     = (i0 - t >= 0) ? __ldg(gpix - t * WH) : -1;
        nb[7 + t]     = (i0 + t < WH) ? __ldg(gpix + t * WH) : -1;
    }

    // ---- Non-critical prefetch (overlaps with rm2/envelope compute) ---------
    const float* pp = pred + b * 8 * NPIX + xy;
    float pr[8];
    #pragma unroll
    for (int c = 0; c < 8; c++) pr[c] = pp[c * NPIX];
    const float w_ign = ign[p];

    if (tid < 16) smax[tid] = 0u;
    s_lab[r0][j] = (unsigned char)lab;

    // ---- rm2: vertical same-label run distance^2 ----------------------------
    {
        unsigned upb = 0, dnb = 0;
        #pragma unroll
        for (int t = 1; t <= 8; t++) {
            if (nb[t - 1] == lab) upb |= 1u << (t - 1);
            if (nb[7 + t] == lab) dnb |= 1u << (t - 1);
        }
        int ru = __ffs(~upb) - 1;       // consecutive same-label run upward
        if (ru == 8) { while (i0 - 1 - ru >= 0 && gpix[-(1 + ru) * WH] == lab) ru++; }
        const int du = (i0 - 1 - ru >= 0) ? ru + 1 : 1000;

        int rd = __ffs(~dnb) - 1;       // downward
        if (rd == 8) { while (i0 + 1 + rd < WH && gpix[(1 + rd) * WH] == lab) rd++; }
        const int dd = (i0 + 1 + rd < WH) ? rd + 1 : 1000;

        const int md = min(du, dd);
        s_rm2[r0][j] = (md >= WH) ? 1e9f : (float)(md * md);
    }
    __syncthreads();

    // ---- Adaptive row envelope (bit-exact early cutoff) ---------------------
    // d^2 = min_{j'} v[j'] + (j-j')^2, v[j'] = (lab'==lab ? rm2[j'] : 0) >= 0.
    float d = 0.f;
    {
        const unsigned char* mrow = s_lab[r0];
        const float*         vrow = s_rm2[r0];
        const unsigned char lb = (unsigned char)lab;
        float m = (lab > 0) ? vrow[j] : 0.f;               // o = 0 term
        for (int o = 1; o < WH; o += 2) {
            float o2a = (float)(o * o);                    // exact integer
            if (__all_sync(0xFFFFFFFFu, o2a >= m)) break;
            int jl = j - o, jr = j + o;
            if (jl >= 0) { float v = (mrow[jl] == lb) ? vrow[jl] : 0.f; m = fminf(m, o2a + v); }
            if (jr < WH) { float v = (mrow[jr] == lb) ? vrow[jr] : 0.f; m = fminf(m, o2a + v); }
            int o1 = o + 1; float o2b = (float)(o1 * o1);
            int jl1 = j - o1, jr1 = j + o1;
            if (jl1 >= 0) { float v = (mrow[jl1] == lb) ? vrow[jl1] : 0.f; m = fminf(m, o2b + v); }
            if (jr1 < WH) { float v = (mrow[jr1] == lb) ? vrow[jr1] : 0.f; m = fminf(m, o2b + v); }
        }
        if (lab > 0) {
            d = __fsqrt_rn(m);                              // IEEE sqrt
            atomicMax(&smax[lab - 1], __float_as_uint(d));  // shared; d>=0
        }
    }
    __syncthreads();
    if (tid < 16 && smax[tid]) atomicMax(&g_max[(b << 4) + tid], smax[tid]);  // REDG

    // ---- Pre-barrier: gt zeros (drain during barrier) + both L1 candidates --
    float* go = out + 1 + b * 8 * NPIX + xy;               // out[0] = loss
    #pragma unroll
    for (int c = 0; c < 8; c++) go[c * NPIX] = 0.f;

    float l1a[8], l1b[8];
    #pragma unroll
    for (int c = 0; c < 8; c++) {
        float da = pr[c];
        float aa = fabsf(da);
        l1a[c] = (aa < 1.f) ? 0.5f * da * da : (aa - 0.5f);
        float db = pr[c] - 1.f;
        float ab = fabsf(db);
        l1b[c] = (ab < 1.f) ? 0.5f * db * db : (ab - 0.5f);
    }

    batchbar(b);   // only this batch's 64 blocks

    // ---- Final maxima: per-warp lane-load + shfl broadcast (no LDS, no bar) -
    const int lane = tid & 31;
    unsigned mraw = (lane < 16) ? __ldcg(&g_max[(b << 4) + lane]) : 0u;

    // ---- Bin select + single hit store + loss (bit-exact term order) --------
    int c0 = -1;
    {
        float mv = __uint_as_float(__shfl_sync(0xFFFFFFFFu, mraw, lab - 1));
        if (lab > 0) {
            float dn = (mv > 0.f) ? __fdiv_rn(d, mv) : d;  // IEEE div
            if (dn < 0.5f) dn = 0.0f;
            if (dn > 0.7f) dn = 1.0f;
            const float DDD[8] = {0.83f, 0.68f, 0.54f, 0.41f, 0.29f, 0.18f, 0.09f, 0.0f};
            c0 = 7;
            #pragma unroll
            for (int c = 0; c < 8; c++)
                if (dn >= DDD[c]) { c0 = c; break; }
            go[c0 * NPIX] = 1.f;     // same thread/address: ordered after the 0
        }
    }

    float s = 0.f;
    #pragma unroll
    for (int c = 0; c < 8; c++)
        s += (c == c0) ? l1b[c] : l1a[c];                  // same terms, same order
    float contrib = w_ign * s * 0.125f;                    // mean over C=8

    #pragma unroll
    for (int off = 16; off; off >>= 1)
        contrib += __shfl_xor_sync(0xFFFFFFFFu, contrib, off);
    if ((tid & 31) == 0) ws[tid >> 5] = contrib;
    __syncthreads();
    if (tid == 0) {
        float tsum = 0.f;
        #pragma unroll
        for (int u = 0; u < 8; u++) tsum += ws[u];
        g_part[bx] = tsum;
        __threadfence();
        unsigned t = atomicAdd(&g_done, 1u);
        s_last = (((t + 1u) & (NBLK - 1u)) == 0u);         // last arrival this replay
    }
    __syncthreads();

    // ---- Last block: reset maxima for next replay + deterministic reduction -
    if (s_last) {
        if (tid < NBK) g_max[tid] = 0u;
        float v = 0.f;
        if (tid < NBLK) {
            v = __ldcg(&g_part[tid]);                      // L2: ordered by producers' fences
            #pragma unroll
            for (int off = 16; off; off >>= 1)
                v += __shfl_xor_sync(0xFFFFFFFFu, v, off);
            if ((tid & 31) == 0) ws[tid >> 5] = v;
        }
        __syncthreads();
        if (tid == 0)
            out[0] = ((ws[0] + ws[1]) + (ws[2] + ws[3])) * (1.f / (float)(NB * NPIX));
    }
}

extern "C" void kernel_launch(void* const* d_in, const int* in_sizes, int n_in,
                              void* d_out, int out_size)
{
    const float* pred = (const float*)d_in[0];   // [2,8,128,128] f32
    const int*   mask = (const int*)  d_in[1];   // [2,128,128]   i32
    const float* ign  = (const float*)d_in[2];   // [2,128,128]   f32
    float* out = (float*)d_out;                  // [0]=loss, [1..]=gt

    fused_kernel<<<NBLK, TPB>>>(pred, mask, ign, out);
}